// round 4
// baseline (speedup 1.0000x reference)
#include <cuda_runtime.h>
#include <math.h>

#define Nn   20000
#define Ee   320000
#define Gg   16
#define TAB  8192
#define RMAXf 4.0f
#define RINf  3.5f
#define PI_F  3.14159265358979f
#define SQRT3f 1.7320508075688772f
#define INV_SQRT3f 0.5773502691896258f

// ---------------- device scratch ----------------
__device__ __align__(16) float g_s  [Nn*64];
__device__ __align__(16) float g_v  [Nn*96];     // [n][c][32]
__device__ __align__(16) float g_s1 [Nn*64];
__device__ __align__(16) float g_v1 [Nn*96];
__device__ __align__(16) float g_scs[Nn*96];     // sc_s / o_s
__device__ __align__(16) float g_scv[Nn*96];     // sc_v / o_v rows (n*3+c) x 32
__device__ __align__(16) float g_as [Nn*96];
__device__ __align__(16) float g_av [Nn*288];    // rows (n*3+c) x 96
__device__ __align__(16) float g_sa [Nn*256];
__device__ __align__(16) float g_va [Nn*384];    // rows (n*3+c) x 128
__device__ __align__(16) float g_tab[(TAB+1)*192];
__device__ float g_atomic[Nn];
__device__ int   g_cnt[Nn];
__device__ int   g_off[Nn+1];
__device__ int   g_cur[Nn];
__device__ int   g_elist[Ee];

__device__ __forceinline__ float silu_f(float x){ return x / (1.0f + expf(-x)); }

// ---------------- init / CSR ----------------
__global__ void k_zero_init(){
    int i = blockIdx.x*256 + threadIdx.x;
    if (i < Nn*96) g_v[i] = 0.0f;
    if (i < Nn)    g_cnt[i] = 0;
}

__global__ void k_count(const int* __restrict__ recv){
    int e = blockIdx.x*256 + threadIdx.x;
    if (e < Ee) atomicAdd(&g_cnt[recv[e]], 1);
}

__global__ void k_scan(){
    __shared__ int sd[1024];
    int t = threadIdx.x;
    int carry = 0;
    for (int base = 0; base < Nn; base += 1024){
        int x = (base+t < Nn) ? g_cnt[base+t] : 0;
        sd[t] = x; __syncthreads();
        #pragma unroll
        for (int o = 1; o < 1024; o <<= 1){
            int y = (t >= o) ? sd[t-o] : 0;
            __syncthreads();
            sd[t] += y;
            __syncthreads();
        }
        int incl = sd[t];
        if (base+t < Nn){ g_off[base+t] = carry + incl - x; g_cur[base+t] = carry + incl - x; }
        int tot = sd[1023];
        __syncthreads();
        carry += tot;
    }
    if (t == 0) g_off[Nn] = carry;
}

__global__ void k_scatter(const int* __restrict__ recv){
    int e = blockIdx.x*256 + threadIdx.x;
    if (e < Ee){
        int p = atomicAdd(&g_cur[recv[e]], 1);
        g_elist[p] = e;
    }
}

__global__ void k_sort(){
    int n = blockIdx.x*256 + threadIdx.x;
    if (n >= Nn) return;
    int b = g_off[n], e2 = g_off[n+1];
    for (int i = b+1; i < e2; i++){
        int key = g_elist[i];
        int j = i-1;
        while (j >= b && g_elist[j] > key){ g_elist[j+1] = g_elist[j]; j--; }
        g_elist[j+1] = key;
    }
}

// ---------------- embedding ----------------
__global__ void k_embed(const float* __restrict__ nodes, const float* __restrict__ Wemb){
    int idx = blockIdx.x*256 + threadIdx.x;
    if (idx >= Nn*64) return;
    int n = idx >> 6, o = idx & 63;
    float acc = 0.f;
    #pragma unroll
    for (int e = 0; e < 4; e++) acc = fmaf(nodes[n*4+e], Wemb[e*64+o], acc);
    g_s[idx] = acc * 0.5f;
}

// ---------------- radial table ----------------
__global__ void k_table(const float* __restrict__ R0, const float* __restrict__ R1,
                        const float* __restrict__ R2){
    __shared__ float h1s[64], h2s[64];
    int row = blockIdx.x, t = threadIdx.x;
    float r = (float)row * (RMAXf / (float)TAB);
    float rs = fmaxf(r, 1e-6f);
    float env;
    if (r < RINf) env = 1.0f;
    else if (r > RMAXf) env = 0.0f;
    else { float tt = (r - RINf) / (RMAXf - RINf); env = 0.5f*(cosf(PI_F*tt)+1.0f); }
    float remb[8];
    #pragma unroll
    for (int nb = 1; nb <= 8; nb++)
        remb[nb-1] = 0.70710678f * sinf((float)nb * PI_F * rs / RMAXf) / rs * env;
    float h = 0.f;
    #pragma unroll
    for (int k = 0; k < 8; k++) h = fmaf(remb[k], R0[k*64+t], h);
    h1s[t] = silu_f(h * 0.35355339f);
    __syncthreads();
    float h2 = 0.f;
    #pragma unroll
    for (int k = 0; k < 64; k++) h2 = fmaf(h1s[k], R1[k*64+t], h2);
    h2s[t] = silu_f(h2 * 0.125f);
    __syncthreads();
    #pragma unroll
    for (int j = 0; j < 3; j++){
        int o = t + 64*j;
        float w = 0.f;
        #pragma unroll 8
        for (int k = 0; k < 64; k++) w = fmaf(h2s[k], R2[k*192+o], w);
        g_tab[row*192+o] = w * 0.125f;
    }
}

// ---------------- outer products ----------------
__global__ void k_build_sa(const float* __restrict__ nodes){
    int idx = blockIdx.x*256 + threadIdx.x;
    if (idx >= Nn*256) return;
    int n = idx >> 8, k = idx & 255, i = k >> 2, e = k & 3;
    g_sa[idx] = g_s[n*64+i] * nodes[n*4+e];
}
__global__ void k_build_va(const float* __restrict__ nodes){
    int idx = blockIdx.x*256 + threadIdx.x;
    if (idx >= Nn*384) return;
    int row = idx >> 7, k = idx & 127, i = k >> 2, e = k & 3;
    int n = row / 3, c = row % 3;
    g_va[idx] = g_v[n*96 + c*32 + i] * nodes[n*4+e];
}

// ---------------- tiled SGEMM: C = A[M,K]@B[K,NC]*alpha (+D) ----------------
template<int K, int NC>
__global__ void k_gemm(const float* __restrict__ A, const float* __restrict__ B,
                       const float* __restrict__ D, float* __restrict__ C,
                       int M, float alpha){
    constexpr int TN = NC / 16;
    __shared__ float As[16][129];
    __shared__ float Bs[16][NC];
    int tid = threadIdx.x;
    int mg = tid & 15, ng = tid >> 4;
    int m0 = blockIdx.x * 128;
    float acc[8][TN];
    #pragma unroll
    for (int i = 0; i < 8; i++)
        #pragma unroll
        for (int j = 0; j < TN; j++) acc[i][j] = 0.f;

    for (int kc = 0; kc < K; kc += 16){
        #pragma unroll
        for (int q = 0; q < 8; q++){
            int e = q*256 + tid;
            int r = e >> 4, c = e & 15;
            int row = m0 + r;
            As[c][r] = (row < M) ? A[row*K + kc + c] : 0.f;
        }
        for (int e = tid; e < 16*NC; e += 256){
            int r = e / NC, c = e % NC;
            Bs[r][c] = B[(kc+r)*NC + c];
        }
        __syncthreads();
        #pragma unroll
        for (int kk = 0; kk < 16; kk++){
            float a[8], b[TN];
            #pragma unroll
            for (int i = 0; i < 8; i++) a[i] = As[kk][mg + 16*i];
            #pragma unroll
            for (int j = 0; j < TN; j++) b[j] = Bs[kk][ng*TN + j];
            #pragma unroll
            for (int i = 0; i < 8; i++)
                #pragma unroll
                for (int j = 0; j < TN; j++) acc[i][j] = fmaf(a[i], b[j], acc[i][j]);
        }
        __syncthreads();
    }
    #pragma unroll
    for (int i = 0; i < 8; i++){
        int row = m0 + mg + 16*i;
        if (row >= M) continue;
        #pragma unroll
        for (int j = 0; j < TN; j++){
            int col = ng*TN + j;
            float v = acc[i][j] * alpha;
            if (D) v += D[row*NC + col];
            C[row*NC + col] = v;
        }
    }
}

// ---------------- fused messages + deterministic gather ----------------
__global__ void k_gather(const float* __restrict__ dR, const int* __restrict__ senders){
    int n = blockIdx.x*8 + threadIdx.y;
    if (n >= Nn) return;
    int l = threadIdx.x;
    int beg = g_off[n], end = g_off[n+1];
    float as0 = 0.f, as1 = 0.f, as2 = 0.f;
    float av00=0,av01=0,av02=0, av10=0,av11=0,av12=0, av20=0,av21=0,av22=0;
    for (int p = beg; p < end; p++){
        int e = g_elist[p];
        float dx = dR[3*e+0], dy = dR[3*e+1], dz = dR[3*e+2];
        float r = sqrtf(dx*dx + dy*dy + dz*dz);
        if (r >= RMAXf) continue;   // MLP has no bias: remb=0 => w=0 exactly
        float inv = 1.0f / fmaxf(r, 1e-6f);
        float shx = SQRT3f*dx*inv, shy = SQRT3f*dy*inv, shz = SQRT3f*dz*inv;
        int src = senders[e];
        float x = r * ((float)TAB / RMAXf);
        int gi = (int)x; if (gi > TAB-1) gi = TAB-1;
        float f = x - (float)gi;
        const float* t0 = g_tab + gi*192;
        const float* t1 = t0 + 192;
        float w1a = fmaf(f, t1[l]      - t0[l],      t0[l]);
        float w1b = fmaf(f, t1[32+l]   - t0[32+l],   t0[32+l]);
        float w2a = fmaf(f, t1[64+l]   - t0[64+l],   t0[64+l]);
        float w2b = fmaf(f, t1[96+l]   - t0[96+l],   t0[96+l]);
        float w3  = fmaf(f, t1[128+l]  - t0[128+l],  t0[128+l]);
        float w4  = fmaf(f, t1[160+l]  - t0[160+l],  t0[160+l]);
        float sea = g_s1[src*64 + l];
        float seb = g_s1[src*64 + 32 + l];
        float ve0 = g_v1[src*96 +      l];
        float ve1 = g_v1[src*96 + 32 + l];
        float ve2 = g_v1[src*96 + 64 + l];
        as0 = fmaf(w1a, sea, as0);
        as1 = fmaf(w1b, seb, as1);
        float dv = ve0*shx + ve1*shy + ve2*shz;
        as2 = fmaf(w4*INV_SQRT3f, dv, as2);
        float p2a = w2a*sea, p2b = w2b*seb;
        av00 = fmaf(p2a, shx, av00); av10 = fmaf(p2a, shy, av10); av20 = fmaf(p2a, shz, av20);
        av01 = fmaf(p2b, shx, av01); av11 = fmaf(p2b, shy, av11); av21 = fmaf(p2b, shz, av21);
        av02 = fmaf(w3, ve0, av02);  av12 = fmaf(w3, ve1, av12);  av22 = fmaf(w3, ve2, av22);
    }
    const float sc = 0.25f;
    g_as[n*96 +      l] = as0*sc;
    g_as[n*96 + 32 + l] = as1*sc;
    g_as[n*96 + 64 + l] = as2*sc;
    int b0 = n*288;
    g_av[b0 +       l] = av00*sc; g_av[b0 +  32+l] = av01*sc; g_av[b0 +  64+l] = av02*sc;
    g_av[b0 +  96 + l] = av10*sc; g_av[b0 + 128+l] = av11*sc; g_av[b0 + 160+l] = av12*sc;
    g_av[b0 + 192 + l] = av20*sc; g_av[b0 + 224+l] = av21*sc; g_av[b0 + 256+l] = av22*sc;
}

// ---------------- activation / gating ----------------
__global__ void k_finalize(){
    __shared__ float gate[32];
    int n = blockIdx.x, t = threadIdx.x;   // 96 threads
    float o = g_scs[n*96 + t];
    if (t < 64) g_s[n*64 + t] = silu_f(o);
    else        gate[t-64] = silu_f(o);
    __syncthreads();
    int j = t & 31;
    g_v[n*96 + t] = g_scv[n*96 + t] * gate[j];
}

// ---------------- heads ----------------
__global__ void k_head(const float* __restrict__ nodes,
                       const float* __restrict__ Wen1, const float* __restrict__ Wen2,
                       const float* __restrict__ Wmag1, const float* __restrict__ Wmag2,
                       const float* __restrict__ sc_occ, const float* __restrict__ sh_occ,
                       const float* __restrict__ esc, const float* __restrict__ esh,
                       float* __restrict__ out){
    int n = blockIdx.x*8 + threadIdx.y;
    if (n >= Nn) return;
    int t = threadIdx.x;
    const float* s = g_s + n*64;
    float he = 0.f, hm = 0.f;
    #pragma unroll 8
    for (int i = 0; i < 64; i++){
        float si = s[i];
        he = fmaf(si, Wen1[i*32+t], he);
        hm = fmaf(si, Wmag1[i*32+t], hm);
    }
    he *= 0.125f; hm *= 0.125f;
    float pe  = he * Wen2[t];
    float pm0 = hm * Wmag2[t*2+0];
    float pm1 = hm * Wmag2[t*2+1];
    #pragma unroll
    for (int o = 16; o; o >>= 1){
        pe  += __shfl_down_sync(0xffffffffu, pe,  o);
        pm0 += __shfl_down_sync(0xffffffffu, pm0, o);
        pm1 += __shfl_down_sync(0xffffffffu, pm1, o);
    }
    if (t == 0){
        g_atomic[n] = esc[0] * (pe * 0.17677669529f) + esh[0];
        float a0 = nodes[n*4+0], a1 = nodes[n*4+1], a2 = nodes[n*4+2];
        float s0 = a0*sc_occ[0] + a1*sc_occ[2] + a2*sc_occ[4];
        float s1m= a0*sc_occ[1] + a1*sc_occ[3] + a2*sc_occ[5];
        float t0 = a0*sh_occ[0] + a1*sh_occ[2] + a2*sh_occ[4];
        float t1 = a0*sh_occ[1] + a1*sh_occ[3] + a2*sh_occ[5];
        out[Gg + n*2 + 0] = s0 *(pm0 * 0.17677669529f) + t0;
        out[Gg + n*2 + 1] = s1m*(pm1 * 0.17677669529f) + t1;
    }
}

__global__ void k_energy(const int* __restrict__ n_node, float* __restrict__ out){
    __shared__ float sm[256];
    int g = blockIdx.x, t = threadIdx.x;
    int start = 0;
    for (int q = 0; q < g; q++) start += n_node[q];
    int end = start + n_node[g];
    if (start > Nn) start = Nn;
    if (end > Nn) end = Nn;
    float acc = 0.f;
    for (int i = start + t; i < end; i += 256) acc += g_atomic[i];
    sm[t] = acc; __syncthreads();
    #pragma unroll
    for (int o = 128; o; o >>= 1){ if (t < o) sm[t] += sm[t+o]; __syncthreads(); }
    if (t == 0) out[g] = sm[0];
}

// ---------------- launch ----------------
extern "C" void kernel_launch(void* const* d_in, const int* in_sizes, int n_in,
                              void* d_out, int out_size){
    const float* nodes   = (const float*)d_in[0];
    const float* dR      = (const float*)d_in[1];
    const int*   senders = (const int*)  d_in[2];
    const int*   recv    = (const int*)  d_in[3];
    const int*   n_node  = (const int*)  d_in[4];
    const float* W_embed = (const float*)d_in[5];
    const float* W_sc_s  = (const float*)d_in[6];
    const float* W_sc_v  = (const float*)d_in[7];
    const float* W_l1_s  = (const float*)d_in[8];
    const float* W_l1_v  = (const float*)d_in[9];
    const float* Wr0     = (const float*)d_in[10];
    const float* Wr1     = (const float*)d_in[11];
    const float* Wr2     = (const float*)d_in[12];
    const float* W_l2_s  = (const float*)d_in[13];
    const float* W_l2_v  = (const float*)d_in[14];
    const float* W_en1   = (const float*)d_in[15];
    const float* W_en2   = (const float*)d_in[16];
    const float* W_mag1  = (const float*)d_in[17];
    const float* W_mag2  = (const float*)d_in[18];
    const float* sc_occ  = (const float*)d_in[19];
    const float* sh_occ  = (const float*)d_in[20];
    const float* esc     = (const float*)d_in[21];
    const float* esh     = (const float*)d_in[22];
    float* out = (float*)d_out;

    // CSR build + init
    k_zero_init<<<(Nn*96 + 255)/256, 256>>>();
    k_count<<<(Ee + 255)/256, 256>>>(recv);
    k_scan<<<1, 1024>>>();
    k_scatter<<<(Ee + 255)/256, 256>>>(recv);
    k_sort<<<(Nn + 255)/256, 256>>>();
    k_embed<<<(Nn*64 + 255)/256, 256>>>(nodes, W_embed);

    float* d_s;  cudaGetSymbolAddress((void**)&d_s,  g_s);
    float* d_v;  cudaGetSymbolAddress((void**)&d_v,  g_v);
    float* d_s1; cudaGetSymbolAddress((void**)&d_s1, g_s1);
    float* d_v1; cudaGetSymbolAddress((void**)&d_v1, g_v1);
    float* d_scs;cudaGetSymbolAddress((void**)&d_scs,g_scs);
    float* d_scv;cudaGetSymbolAddress((void**)&d_scv,g_scv);
    float* d_as; cudaGetSymbolAddress((void**)&d_as, g_as);
    float* d_av; cudaGetSymbolAddress((void**)&d_av, g_av);
    float* d_sa; cudaGetSymbolAddress((void**)&d_sa, g_sa);
    float* d_va; cudaGetSymbolAddress((void**)&d_va, g_va);

    const float a_scs = 0.0625f;         // 1/sqrt(256)
    const float a_scv = 0.08838834764f;  // 1/sqrt(128)
    const float a_s1  = 0.125f;          // 1/sqrt(64)
    const float a_v1  = 0.17677669529f;  // 1/sqrt(32)
    const float a_o   = 0.10206207262f;  // 1/sqrt(96)

    for (int l = 0; l < 2; l++){
        k_build_sa<<<(Nn*256 + 255)/256, 256>>>(nodes);
        k_build_va<<<(Nn*384 + 255)/256, 256>>>(nodes);
        k_gemm<256,96><<<(Nn + 127)/128, 256>>>(d_sa, W_sc_s + l*24576, nullptr, d_scs, Nn,   a_scs);
        k_gemm<128,32><<<(3*Nn + 127)/128, 256>>>(d_va, W_sc_v + l*4096, nullptr, d_scv, 3*Nn, a_scv);
        k_gemm< 64,64><<<(Nn + 127)/128, 256>>>(d_s,  W_l1_s + l*4096,  nullptr, d_s1,  Nn,   a_s1);
        k_gemm< 32,32><<<(3*Nn + 127)/128, 256>>>(d_v,  W_l1_v + l*1024,  nullptr, d_v1,  3*Nn, a_v1);
        k_table<<<TAB + 1, 64>>>(Wr0 + l*512, Wr1 + l*4096, Wr2 + l*12288);
        k_gather<<<(Nn + 7)/8, dim3(32, 8)>>>(dR, senders);
        k_gemm< 96,96><<<(Nn + 127)/128, 256>>>(d_as, W_l2_s + l*9216, d_scs, d_scs, Nn,   a_o);
        k_gemm< 96,32><<<(3*Nn + 127)/128, 256>>>(d_av, W_l2_v + l*3072, d_scv, d_scv, 3*Nn, a_o);
        k_finalize<<<Nn, 96>>>();
    }

    k_head<<<(Nn + 7)/8, dim3(32, 8)>>>(nodes, W_en1, W_en2, W_mag1, W_mag2,
                                        sc_occ, sh_occ, esc, esh, out);
    k_energy<<<Gg, 256>>>(n_node, out);
}

// round 5
// speedup vs baseline: 1.1900x; 1.1900x over previous
#include <cuda_runtime.h>
#include <cuda_fp16.h>
#include <math.h>

#define Nn   20000
#define Ee   320000
#define Gg   16
#define TAB  8192
#define RMAXf 4.0f
#define RINf  3.5f
#define PI_F  3.14159265358979f
#define SQRT3f 1.7320508075688772f
#define INV_SQRT3f 0.5773502691896258f

// ---------------- device scratch ----------------
__device__ __align__(16) float g_s  [Nn*64];
__device__ __align__(16) float g_v  [Nn*96];     // [n][c][32] == row (n*3+c) x 32
__device__ __align__(16) float g_s1 [Nn*64];
__device__ __align__(16) float g_v1 [Nn*96];
__device__ __align__(16) float g_scs[Nn*96];
__device__ __align__(16) float g_scv[Nn*96];
__device__ __align__(16) float g_as [Nn*96];
__device__ __align__(16) float g_av [Nn*288];
__device__ __align__(16) float g_gate[Nn*32];
__device__ __align__(16) float g_tab [2*(TAB+1)*192];
__device__ __align__(16) __half2 g_tabh[2*TAB*192];
__device__ float g_atomic[Nn];
__device__ int   g_cnt[Nn];
__device__ int   g_off[Nn+1];
__device__ int   g_cur[Nn];
__device__ int   g_elist[Ee];

__device__ __forceinline__ float silu_f(float x){ return x / (1.0f + expf(-x)); }

// ---------------- init / CSR ----------------
__global__ void k_zero_init(){
    int i = blockIdx.x*256 + threadIdx.x;
    if (i < Nn*96) g_v[i] = 0.0f;
    if (i < Nn)    g_cnt[i] = 0;
}

__global__ void k_count(const int* __restrict__ recv){
    int e = blockIdx.x*256 + threadIdx.x;
    if (e < Ee) atomicAdd(&g_cnt[recv[e]], 1);
}

// single-block warp-shuffle scan: 1024 threads x 20 elements
__global__ void k_scan(){
    const int PER = 20;
    int t = threadIdx.x;
    int base = t * PER;
    int loc[PER]; int s = 0;
    #pragma unroll
    for (int i = 0; i < PER; i++){
        int idx = base + i;
        int x = (idx < Nn) ? g_cnt[idx] : 0;
        loc[i] = s; s += x;
    }
    int lane = t & 31, wid = t >> 5;
    int v = s;
    #pragma unroll
    for (int o = 1; o < 32; o <<= 1){
        int y = __shfl_up_sync(0xffffffffu, v, o);
        if (lane >= o) v += y;
    }
    __shared__ int wsum[32];
    if (lane == 31) wsum[wid] = v;
    __syncthreads();
    if (wid == 0){
        int w = wsum[lane];
        #pragma unroll
        for (int o = 1; o < 32; o <<= 1){
            int y = __shfl_up_sync(0xffffffffu, w, o);
            if (lane >= o) w += y;
        }
        wsum[lane] = w;
    }
    __syncthreads();
    int excl = v - s + (wid ? wsum[wid-1] : 0);
    #pragma unroll
    for (int i = 0; i < PER; i++){
        int idx = base + i;
        int off = excl + loc[i];
        if (idx < Nn){ g_off[idx] = off; g_cur[idx] = off; }
        else if (idx == Nn) g_off[Nn] = off;
    }
}

__global__ void k_scatter(const int* __restrict__ recv){
    int e = blockIdx.x*256 + threadIdx.x;
    if (e < Ee){
        int p = atomicAdd(&g_cur[recv[e]], 1);
        g_elist[p] = e;
    }
}

__global__ void k_sort(){
    int n = blockIdx.x*256 + threadIdx.x;
    if (n >= Nn) return;
    int b = g_off[n], e2 = g_off[n+1];
    for (int i = b+1; i < e2; i++){
        int key = g_elist[i];
        int j = i-1;
        while (j >= b && g_elist[j] > key){ g_elist[j+1] = g_elist[j]; j--; }
        g_elist[j+1] = key;
    }
}

// ---------------- embedding ----------------
__global__ void k_embed(const float* __restrict__ nodes, const float* __restrict__ Wemb){
    int idx = blockIdx.x*256 + threadIdx.x;
    if (idx >= Nn*64) return;
    int n = idx >> 6, o = idx & 63;
    float acc = 0.f;
    #pragma unroll
    for (int e = 0; e < 4; e++) acc = fmaf(nodes[n*4+e], Wemb[e*64+o], acc);
    g_s[idx] = acc * 0.5f;
}

// ---------------- radial table (both layers) ----------------
__global__ void k_table2(const float* __restrict__ Wr0, const float* __restrict__ Wr1,
                         const float* __restrict__ Wr2){
    __shared__ float h1s[64], h2s[64];
    int l   = blockIdx.x / (TAB+1);
    int row = blockIdx.x % (TAB+1);
    int t = threadIdx.x;
    const float* R0 = Wr0 + l*512;
    const float* R1 = Wr1 + l*4096;
    const float* R2 = Wr2 + l*12288;
    float r = (float)row * (RMAXf / (float)TAB);
    float rs = fmaxf(r, 1e-6f);
    float env;
    if (r < RINf) env = 1.0f;
    else if (r > RMAXf) env = 0.0f;
    else { float tt = (r - RINf) / (RMAXf - RINf); env = 0.5f*(cosf(PI_F*tt)+1.0f); }
    float remb[8];
    #pragma unroll
    for (int nb = 1; nb <= 8; nb++)
        remb[nb-1] = 0.70710678f * sinf((float)nb * PI_F * rs / RMAXf) / rs * env;
    float h = 0.f;
    #pragma unroll
    for (int k = 0; k < 8; k++) h = fmaf(remb[k], R0[k*64+t], h);
    h1s[t] = silu_f(h * 0.35355339f);
    __syncthreads();
    float h2 = 0.f;
    #pragma unroll
    for (int k = 0; k < 64; k++) h2 = fmaf(h1s[k], R1[k*64+t], h2);
    h2s[t] = silu_f(h2 * 0.125f);
    __syncthreads();
    #pragma unroll
    for (int j = 0; j < 3; j++){
        int o = t + 64*j;
        float w = 0.f;
        #pragma unroll 8
        for (int k = 0; k < 64; k++) w = fmaf(h2s[k], R2[k*192+o], w);
        g_tab[(l*(TAB+1) + row)*192 + o] = w * 0.125f;
    }
}

__global__ void k_pack(){
    int idx = blockIdx.x*256 + threadIdx.x;
    if (idx >= 2*TAB*192) return;
    int l   = idx / (TAB*192);
    int rem = idx % (TAB*192);
    int row = rem / 192, o = rem % 192;
    float v0 = g_tab[(l*(TAB+1) + row    )*192 + o];
    float v1 = g_tab[(l*(TAB+1) + row + 1)*192 + o];
    g_tabh[idx] = __floats2half2_rn(v0, v1 - v0);
}

// ---------------- tiled SGEMM with fused modes ----------------
// MODE 0: C = A@B * alpha
// MODE 1: A[row,k] = Abase[row*(K/4) + (k>>2)] * attrs[row*4 + (k&3)]         (sc_s)
// MODE 4: A[row,k] = Abase[row*32  + (k>>2)] * attrs[(row/3)*4 + (k&3)]       (sc_v)
// MODE 2: o_s epilogue: val = acc*alpha + D;  silu -> g_s (col<64) / g_gate
// MODE 3: o_v epilogue: val = acc*alpha + D;  g_v = val * g_gate[row/3]
template<int K, int NC, int MODE>
__global__ __launch_bounds__(256, 2)
void k_gemm(const float* __restrict__ A, const float* __restrict__ B,
            const float* __restrict__ D, float* __restrict__ C,
            const float* __restrict__ attrs, int M, float alpha){
    constexpr int TN = NC / 16;
    __shared__ float As[16][129];
    __shared__ float Bs[16][NC];
    int tid = threadIdx.x;
    int mg = tid & 15, ng = tid >> 4;
    int m0 = blockIdx.x * 128;
    float acc[8][TN];
    #pragma unroll
    for (int i = 0; i < 8; i++)
        #pragma unroll
        for (int j = 0; j < TN; j++) acc[i][j] = 0.f;

    for (int kc = 0; kc < K; kc += 16){
        #pragma unroll
        for (int q = 0; q < 8; q++){
            int e2 = q*256 + tid;
            int r = e2 >> 4, c = e2 & 15;
            int row = m0 + r;
            float val = 0.f;
            if (row < M){
                int k = kc + c;
                if (MODE == 1){
                    val = A[row*(K/4) + (k>>2)] * attrs[row*4 + (k&3)];
                } else if (MODE == 4){
                    val = A[row*32 + (k>>2)] * attrs[(row/3)*4 + (k&3)];
                } else {
                    val = A[row*K + k];
                }
            }
            As[c][r] = val;
        }
        for (int e2 = tid; e2 < 16*NC; e2 += 256){
            int r = e2 / NC, c = e2 % NC;
            Bs[r][c] = B[(kc+r)*NC + c];
        }
        __syncthreads();
        #pragma unroll
        for (int kk = 0; kk < 16; kk++){
            float a[8], b[TN];
            #pragma unroll
            for (int i = 0; i < 8; i++) a[i] = As[kk][mg + 16*i];
            #pragma unroll
            for (int j = 0; j < TN; j++) b[j] = Bs[kk][ng*TN + j];
            #pragma unroll
            for (int i = 0; i < 8; i++)
                #pragma unroll
                for (int j = 0; j < TN; j++) acc[i][j] = fmaf(a[i], b[j], acc[i][j]);
        }
        __syncthreads();
    }
    #pragma unroll
    for (int i = 0; i < 8; i++){
        int row = m0 + mg + 16*i;
        if (row >= M) continue;
        #pragma unroll
        for (int j = 0; j < TN; j++){
            int col = ng*TN + j;
            float val = acc[i][j] * alpha;
            if (MODE == 2){
                val += D[row*96 + col];
                float sv = silu_f(val);
                if (col < 64) g_s[row*64 + col] = sv;
                else          g_gate[row*32 + (col-64)] = sv;
            } else if (MODE == 3){
                val += D[row*32 + col];
                g_v[row*32 + col] = val * g_gate[(row/3)*32 + col];
            } else {
                C[row*NC + col] = val;
            }
        }
    }
}

// ---------------- fused messages + deterministic gather ----------------
__global__ void k_gather(const float* __restrict__ dR, const int* __restrict__ senders,
                         int layer){
    int n = blockIdx.x*8 + threadIdx.y;
    if (n >= Nn) return;
    int l = threadIdx.x;
    const __half2* tb_base = g_tabh + layer*(TAB*192);
    int beg = g_off[n], end = g_off[n+1];
    float as0 = 0.f, as1 = 0.f, as2 = 0.f;
    float av00=0,av01=0,av02=0, av10=0,av11=0,av12=0, av20=0,av21=0,av22=0;
    for (int p = beg; p < end; p++){
        int e = g_elist[p];
        float dx = dR[3*e+0], dy = dR[3*e+1], dz = dR[3*e+2];
        float r = sqrtf(dx*dx + dy*dy + dz*dz);
        if (r >= RMAXf) continue;   // radial weights exactly 0 beyond cutoff
        float inv = 1.0f / fmaxf(r, 1e-6f);
        float shx = SQRT3f*dx*inv, shy = SQRT3f*dy*inv, shz = SQRT3f*dz*inv;
        int src = senders[e];
        float x = r * ((float)TAB / RMAXf);
        int gi = (int)x; if (gi > TAB-1) gi = TAB-1;
        float f = x - (float)gi;
        const __half2* t0 = tb_base + gi*192;
        __half2 h1a = t0[l],       h1b = t0[32+l];
        __half2 h2a = t0[64+l],    h2b = t0[96+l];
        __half2 h3  = t0[128+l],   h4  = t0[160+l];
        float w1a = __low2float(h1a) + f*__high2float(h1a);
        float w1b = __low2float(h1b) + f*__high2float(h1b);
        float w2a = __low2float(h2a) + f*__high2float(h2a);
        float w2b = __low2float(h2b) + f*__high2float(h2b);
        float w3  = __low2float(h3)  + f*__high2float(h3);
        float w4  = __low2float(h4)  + f*__high2float(h4);
        float sea = g_s1[src*64 + l];
        float seb = g_s1[src*64 + 32 + l];
        float ve0 = g_v1[src*96 +      l];
        float ve1 = g_v1[src*96 + 32 + l];
        float ve2 = g_v1[src*96 + 64 + l];
        as0 = fmaf(w1a, sea, as0);
        as1 = fmaf(w1b, seb, as1);
        float dv = ve0*shx + ve1*shy + ve2*shz;
        as2 = fmaf(w4*INV_SQRT3f, dv, as2);
        float p2a = w2a*sea, p2b = w2b*seb;
        av00 = fmaf(p2a, shx, av00); av10 = fmaf(p2a, shy, av10); av20 = fmaf(p2a, shz, av20);
        av01 = fmaf(p2b, shx, av01); av11 = fmaf(p2b, shy, av11); av21 = fmaf(p2b, shz, av21);
        av02 = fmaf(w3, ve0, av02);  av12 = fmaf(w3, ve1, av12);  av22 = fmaf(w3, ve2, av22);
    }
    const float sc = 0.25f;
    g_as[n*96 +      l] = as0*sc;
    g_as[n*96 + 32 + l] = as1*sc;
    g_as[n*96 + 64 + l] = as2*sc;
    int b0 = n*288;
    g_av[b0 +       l] = av00*sc; g_av[b0 +  32+l] = av01*sc; g_av[b0 +  64+l] = av02*sc;
    g_av[b0 +  96 + l] = av10*sc; g_av[b0 + 128+l] = av11*sc; g_av[b0 + 160+l] = av12*sc;
    g_av[b0 + 192 + l] = av20*sc; g_av[b0 + 224+l] = av21*sc; g_av[b0 + 256+l] = av22*sc;
}

// ---------------- heads ----------------
__global__ void k_head(const float* __restrict__ nodes,
                       const float* __restrict__ Wen1, const float* __restrict__ Wen2,
                       const float* __restrict__ Wmag1, const float* __restrict__ Wmag2,
                       const float* __restrict__ sc_occ, const float* __restrict__ sh_occ,
                       const float* __restrict__ esc, const float* __restrict__ esh,
                       float* __restrict__ out){
    int n = blockIdx.x*8 + threadIdx.y;
    if (n >= Nn) return;
    int t = threadIdx.x;
    const float* s = g_s + n*64;
    float he = 0.f, hm = 0.f;
    #pragma unroll 8
    for (int i = 0; i < 64; i++){
        float si = s[i];
        he = fmaf(si, Wen1[i*32+t], he);
        hm = fmaf(si, Wmag1[i*32+t], hm);
    }
    he *= 0.125f; hm *= 0.125f;
    float pe  = he * Wen2[t];
    float pm0 = hm * Wmag2[t*2+0];
    float pm1 = hm * Wmag2[t*2+1];
    #pragma unroll
    for (int o = 16; o; o >>= 1){
        pe  += __shfl_down_sync(0xffffffffu, pe,  o);
        pm0 += __shfl_down_sync(0xffffffffu, pm0, o);
        pm1 += __shfl_down_sync(0xffffffffu, pm1, o);
    }
    if (t == 0){
        g_atomic[n] = esc[0] * (pe * 0.17677669529f) + esh[0];
        float a0 = nodes[n*4+0], a1 = nodes[n*4+1], a2 = nodes[n*4+2];
        float s0 = a0*sc_occ[0] + a1*sc_occ[2] + a2*sc_occ[4];
        float s1m= a0*sc_occ[1] + a1*sc_occ[3] + a2*sc_occ[5];
        float t0 = a0*sh_occ[0] + a1*sh_occ[2] + a2*sh_occ[4];
        float t1 = a0*sh_occ[1] + a1*sh_occ[3] + a2*sh_occ[5];
        out[Gg + n*2 + 0] = s0 *(pm0 * 0.17677669529f) + t0;
        out[Gg + n*2 + 1] = s1m*(pm1 * 0.17677669529f) + t1;
    }
}

__global__ void k_energy(const int* __restrict__ n_node, float* __restrict__ out){
    __shared__ float sm[256];
    int g = blockIdx.x, t = threadIdx.x;
    int start = 0;
    for (int q = 0; q < g; q++) start += n_node[q];
    int end = start + n_node[g];
    if (start > Nn) start = Nn;
    if (end > Nn) end = Nn;
    float acc = 0.f;
    for (int i = start + t; i < end; i += 256) acc += g_atomic[i];
    sm[t] = acc; __syncthreads();
    #pragma unroll
    for (int o = 128; o; o >>= 1){ if (t < o) sm[t] += sm[t+o]; __syncthreads(); }
    if (t == 0) out[g] = sm[0];
}

// ---------------- launch ----------------
extern "C" void kernel_launch(void* const* d_in, const int* in_sizes, int n_in,
                              void* d_out, int out_size){
    const float* nodes   = (const float*)d_in[0];
    const float* dR      = (const float*)d_in[1];
    const int*   senders = (const int*)  d_in[2];
    const int*   recv    = (const int*)  d_in[3];
    const int*   n_node  = (const int*)  d_in[4];
    const float* W_embed = (const float*)d_in[5];
    const float* W_sc_s  = (const float*)d_in[6];
    const float* W_sc_v  = (const float*)d_in[7];
    const float* W_l1_s  = (const float*)d_in[8];
    const float* W_l1_v  = (const float*)d_in[9];
    const float* Wr0     = (const float*)d_in[10];
    const float* Wr1     = (const float*)d_in[11];
    const float* Wr2     = (const float*)d_in[12];
    const float* W_l2_s  = (const float*)d_in[13];
    const float* W_l2_v  = (const float*)d_in[14];
    const float* W_en1   = (const float*)d_in[15];
    const float* W_en2   = (const float*)d_in[16];
    const float* W_mag1  = (const float*)d_in[17];
    const float* W_mag2  = (const float*)d_in[18];
    const float* sc_occ  = (const float*)d_in[19];
    const float* sh_occ  = (const float*)d_in[20];
    const float* esc     = (const float*)d_in[21];
    const float* esh     = (const float*)d_in[22];
    float* out = (float*)d_out;

    k_zero_init<<<(Nn*96 + 255)/256, 256>>>();
    k_count<<<(Ee + 255)/256, 256>>>(recv);
    k_scan<<<1, 1024>>>();
    k_scatter<<<(Ee + 255)/256, 256>>>(recv);
    k_sort<<<(Nn + 255)/256, 256>>>();
    k_embed<<<(Nn*64 + 255)/256, 256>>>(nodes, W_embed);
    k_table2<<<2*(TAB+1), 64>>>(Wr0, Wr1, Wr2);
    k_pack<<<(2*TAB*192 + 255)/256, 256>>>();

    float* d_s;  cudaGetSymbolAddress((void**)&d_s,  g_s);
    float* d_v;  cudaGetSymbolAddress((void**)&d_v,  g_v);
    float* d_s1; cudaGetSymbolAddress((void**)&d_s1, g_s1);
    float* d_v1; cudaGetSymbolAddress((void**)&d_v1, g_v1);
    float* d_scs;cudaGetSymbolAddress((void**)&d_scs,g_scs);
    float* d_scv;cudaGetSymbolAddress((void**)&d_scv,g_scv);
    float* d_as; cudaGetSymbolAddress((void**)&d_as, g_as);
    float* d_av; cudaGetSymbolAddress((void**)&d_av, g_av);

    const float a_scs = 0.0625f;         // 1/sqrt(256)
    const float a_scv = 0.08838834764f;  // 1/sqrt(128)
    const float a_s1  = 0.125f;          // 1/sqrt(64)
    const float a_v1  = 0.17677669529f;  // 1/sqrt(32)
    const float a_o   = 0.10206207262f;  // 1/sqrt(96)

    for (int l = 0; l < 2; l++){
        k_gemm<256,96,1><<<(Nn + 127)/128, 256>>>(d_s, W_sc_s + l*24576, nullptr, d_scs, nodes, Nn,   a_scs);
        k_gemm<128,32,4><<<(3*Nn + 127)/128, 256>>>(d_v, W_sc_v + l*4096,  nullptr, d_scv, nodes, 3*Nn, a_scv);
        k_gemm< 64,64,0><<<(Nn + 127)/128, 256>>>(d_s, W_l1_s + l*4096,  nullptr, d_s1,  nullptr, Nn,   a_s1);
        k_gemm< 32,32,0><<<(3*Nn + 127)/128, 256>>>(d_v, W_l1_v + l*1024,  nullptr, d_v1,  nullptr, 3*Nn, a_v1);
        k_gather<<<(Nn + 7)/8, dim3(32, 8)>>>(dR, senders, l);
        k_gemm< 96,96,2><<<(Nn + 127)/128, 256>>>(d_as, W_l2_s + l*9216, d_scs, nullptr, nullptr, Nn,   a_o);
        k_gemm< 96,32,3><<<(3*Nn + 127)/128, 256>>>(d_av, W_l2_v + l*3072, d_scv, nullptr, nullptr, 3*Nn, a_o);
    }

    k_head<<<(Nn + 7)/8, dim3(32, 8)>>>(nodes, W_en1, W_en2, W_mag1, W_mag2,
                                        sc_occ, sh_occ, esc, esh, out);
    k_energy<<<Gg, 256>>>(n_node, out);
}

// round 6
// speedup vs baseline: 1.8397x; 1.5459x over previous
#include <cuda_runtime.h>
#include <cuda_fp16.h>
#include <math.h>

#define Nn   20000
#define Ee   320000
#define Gg   16
#define TAB  8192
#define RMAXf 4.0f
#define RINf  3.5f
#define PI_F  3.14159265358979f
#define SQRT3f 1.7320508075688772f
#define INV_SQRT3f 0.5773502691896258f

#define NBs 157   // (Nn+127)/128
#define NBv 469   // (3*Nn+127)/128

// ---------------- device scratch ----------------
__device__ __align__(16) float g_s  [Nn*64];
__device__ __align__(16) float g_v  [Nn*96];     // raw o_v, rows (n*3+c) x 32
__device__ __align__(16) float g_s1 [Nn*64];
__device__ __align__(16) float g_v1 [Nn*96];
__device__ __align__(16) float g_scs[Nn*96];
__device__ __align__(16) float g_as [Nn*96];
__device__ __align__(16) float g_av [Nn*288];
__device__ __align__(16) float g_gate[Nn*32];
__device__ __align__(16) float g_tab [2*(TAB+1)*192];
__device__ __align__(16) __half2 g_tabh[2*TAB*192];
__device__ float g_atomic[Nn];
__device__ int   g_cnt[Nn];
__device__ int   g_off[Nn+1];
__device__ int   g_cur[Nn];
__device__ int   g_elist[Ee];

__device__ __forceinline__ float silu_f(float x){ return x / (1.0f + expf(-x)); }

// ---------------- CSR ----------------
__global__ void k_zero_init(){
    int i = blockIdx.x*256 + threadIdx.x;
    if (i < Nn) g_cnt[i] = 0;
}

__global__ void k_count(const int* __restrict__ recv){
    int e = blockIdx.x*256 + threadIdx.x;
    if (e < Ee) atomicAdd(&g_cnt[recv[e]], 1);
}

__global__ void k_scan(){
    const int PER = 20;
    int t = threadIdx.x;
    int base = t * PER;
    int loc[PER]; int s = 0;
    #pragma unroll
    for (int i = 0; i < PER; i++){
        int idx = base + i;
        int x = (idx < Nn) ? g_cnt[idx] : 0;
        loc[i] = s; s += x;
    }
    int lane = t & 31, wid = t >> 5;
    int v = s;
    #pragma unroll
    for (int o = 1; o < 32; o <<= 1){
        int y = __shfl_up_sync(0xffffffffu, v, o);
        if (lane >= o) v += y;
    }
    __shared__ int wsum[32];
    if (lane == 31) wsum[wid] = v;
    __syncthreads();
    if (wid == 0){
        int w = wsum[lane];
        #pragma unroll
        for (int o = 1; o < 32; o <<= 1){
            int y = __shfl_up_sync(0xffffffffu, w, o);
            if (lane >= o) w += y;
        }
        wsum[lane] = w;
    }
    __syncthreads();
    int excl = v - s + (wid ? wsum[wid-1] : 0);
    #pragma unroll
    for (int i = 0; i < PER; i++){
        int idx = base + i;
        int off = excl + loc[i];
        if (idx < Nn){ g_off[idx] = off; g_cur[idx] = off; }
        else if (idx == Nn) g_off[Nn] = off;
    }
}

__global__ void k_scatter(const int* __restrict__ recv){
    int e = blockIdx.x*256 + threadIdx.x;
    if (e < Ee){
        int p = atomicAdd(&g_cur[recv[e]], 1);
        g_elist[p] = e;
    }
}

// ---------------- misc fused: sort | embed | table ----------------
#define SORT_NB  79          // (Nn+255)/256
#define EMB_NB   5000        // Nn*64/256
#define TROWS    (2*(TAB+1))
#define TAB_NB   ((TROWS+3)/4)

__global__ void k_misc(const float* __restrict__ nodes, const float* __restrict__ Wemb,
                       const float* __restrict__ Wr0, const float* __restrict__ Wr1,
                       const float* __restrict__ Wr2){
    __shared__ float h1s[4][64];
    __shared__ float h2s[4][64];
    int blk = blockIdx.x;
    int tid = threadIdx.x;
    if (blk < SORT_NB){
        int n = blk*256 + tid;
        if (n < Nn){
            int b = g_off[n], e2 = g_off[n+1];
            for (int i = b+1; i < e2; i++){
                int key = g_elist[i];
                int j = i-1;
                while (j >= b && g_elist[j] > key){ g_elist[j+1] = g_elist[j]; j--; }
                g_elist[j+1] = key;
            }
        }
    } else if (blk < SORT_NB + EMB_NB){
        int idx = (blk - SORT_NB)*256 + tid;
        int n = idx >> 6, o = idx & 63;
        float acc = 0.f;
        #pragma unroll
        for (int e = 0; e < 4; e++) acc = fmaf(nodes[n*4+e], Wemb[e*64+o], acc);
        g_s[idx] = acc * 0.5f;
    } else {
        int q = (blk - SORT_NB - EMB_NB)*4 + (tid >> 6);
        int t = tid & 63, sub = tid >> 6;
        bool act = (q < TROWS);
        int l = act ? q / (TAB+1) : 0;
        int row = act ? q % (TAB+1) : 0;
        const float* R0 = Wr0 + l*512;
        const float* R1 = Wr1 + l*4096;
        const float* R2 = Wr2 + l*12288;
        float r = (float)row * (RMAXf / (float)TAB);
        float rs = fmaxf(r, 1e-6f);
        float env;
        if (r < RINf) env = 1.0f;
        else if (r > RMAXf) env = 0.0f;
        else { float tt = (r - RINf) / (RMAXf - RINf); env = 0.5f*(cosf(PI_F*tt)+1.0f); }
        float remb[8];
        #pragma unroll
        for (int nb = 1; nb <= 8; nb++)
            remb[nb-1] = 0.70710678f * sinf((float)nb * PI_F * rs / RMAXf) / rs * env;
        float h = 0.f;
        #pragma unroll
        for (int k = 0; k < 8; k++) h = fmaf(remb[k], R0[k*64+t], h);
        h1s[sub][t] = silu_f(h * 0.35355339f);
        __syncthreads();
        float h2 = 0.f;
        #pragma unroll
        for (int k = 0; k < 64; k++) h2 = fmaf(h1s[sub][k], R1[k*64+t], h2);
        h2s[sub][t] = silu_f(h2 * 0.125f);
        __syncthreads();
        if (act){
            #pragma unroll
            for (int j = 0; j < 3; j++){
                int o = t + 64*j;
                float w = 0.f;
                #pragma unroll 8
                for (int k = 0; k < 64; k++) w = fmaf(h2s[sub][k], R2[k*192+o], w);
                g_tab[q*192 + o] = w * 0.125f;
            }
        }
    }
}

__global__ void k_pack(){
    int idx = blockIdx.x*256 + threadIdx.x;
    if (idx >= 2*TAB*192) return;
    int l   = idx / (TAB*192);
    int rem = idx % (TAB*192);
    int row = rem / 192, o = rem % 192;
    float v0 = g_tab[(l*(TAB+1) + row    )*192 + o];
    float v1 = g_tab[(l*(TAB+1) + row + 1)*192 + o];
    g_tabh[idx] = __floats2half2_rn(v0, v1 - v0);
}

// ---------------- gemm body ----------------
// MODE 0: plain C = acc*alpha
// MODE 1: loader A[row,k] = A[row*64 + (k>>2)] * attrs[row*4 + (k&3)]   (sc_s, K=256)
// MODE 5: loader A[row,k] = A[row*32 + k] * attrs[(row/3)*32 + k]       (gated l1_v)
// MODE 2: epilogue val = acc*alpha + D[row*96+col]; silu -> g_s / g_gate
template<int K, int NC, int MODE>
__device__ __forceinline__ void gemm_body(float* sm,
            const float* __restrict__ A, const float* __restrict__ B,
            const float* __restrict__ D, float* __restrict__ C,
            const float* __restrict__ attrs, int M, float alpha, int blk){
    constexpr int TN = NC / 16;
    float* As = sm;                 // [16][129]
    float* Bs = sm + 16*129;        // [16][NC]
    int tid = threadIdx.x;
    int mg = tid & 15, ng = tid >> 4;
    int m0 = blk * 128;
    float acc[8][TN];
    #pragma unroll
    for (int i = 0; i < 8; i++)
        #pragma unroll
        for (int j = 0; j < TN; j++) acc[i][j] = 0.f;

    for (int kc = 0; kc < K; kc += 16){
        #pragma unroll
        for (int q = 0; q < 8; q++){
            int e2 = q*256 + tid;
            int r = e2 >> 4, c = e2 & 15;
            int row = m0 + r;
            float val = 0.f;
            if (row < M){
                int k = kc + c;
                if (MODE == 1)      val = A[row*64 + (k>>2)] * attrs[row*4 + (k&3)];
                else if (MODE == 5) val = A[row*32 + k] * attrs[(row/3)*32 + k];
                else                val = A[row*K + k];
            }
            As[c*129 + r] = val;
        }
        for (int e2 = tid; e2 < 16*NC; e2 += 256){
            int r = e2 / NC, c = e2 % NC;
            Bs[r*NC + c] = B[(kc+r)*NC + c];
        }
        __syncthreads();
        #pragma unroll
        for (int kk = 0; kk < 16; kk++){
            float a[8], b[TN];
            #pragma unroll
            for (int i = 0; i < 8; i++) a[i] = As[kk*129 + mg + 16*i];
            #pragma unroll
            for (int j = 0; j < TN; j++) b[j] = Bs[kk*NC + ng*TN + j];
            #pragma unroll
            for (int i = 0; i < 8; i++)
                #pragma unroll
                for (int j = 0; j < TN; j++) acc[i][j] = fmaf(a[i], b[j], acc[i][j]);
        }
        __syncthreads();
    }
    #pragma unroll
    for (int i = 0; i < 8; i++){
        int row = m0 + mg + 16*i;
        if (row >= M) continue;
        #pragma unroll
        for (int j = 0; j < TN; j++){
            int col = ng*TN + j;
            float val = acc[i][j] * alpha;
            if (MODE == 2){
                val += D[row*96 + col];
                float sv = silu_f(val);
                if (col < 64) g_s[row*64 + col] = sv;
                else          g_gate[row*32 + (col-64)] = sv;
            } else {
                C[row*NC + col] = val;
            }
        }
    }
}

#define A_SCS 0.0625f
#define A_S1  0.125f
#define A_V1  0.17677669529f
#define A_O   0.10206207262f

// phase A, layer 0: sc_s | l1_s
__global__ __launch_bounds__(256, 2)
void k_phA0(const float* __restrict__ nodes, const float* __restrict__ WscS,
            const float* __restrict__ Wl1s){
    __shared__ float sm[16*129 + 16*96];
    int b = blockIdx.x;
    if (b < NBs) gemm_body<256,96,1>(sm, g_s, WscS, nullptr, g_scs, nodes, Nn, A_SCS, b);
    else         gemm_body< 64,64,0>(sm, g_s, Wl1s, nullptr, g_s1, nullptr, Nn, A_S1, b-NBs);
}

// phase A, layer 1: sc_s | l1_s | gated l1_v
__global__ __launch_bounds__(256, 2)
void k_phA1(const float* __restrict__ nodes, const float* __restrict__ WscS,
            const float* __restrict__ Wl1s, const float* __restrict__ Wl1v){
    __shared__ float sm[16*129 + 16*96];
    int b = blockIdx.x;
    if (b < NBs)        gemm_body<256,96,1>(sm, g_s, WscS, nullptr, g_scs, nodes, Nn, A_SCS, b);
    else if (b < 2*NBs) gemm_body< 64,64,0>(sm, g_s, Wl1s, nullptr, g_s1, nullptr, Nn, A_S1, b-NBs);
    else                gemm_body< 32,32,5>(sm, g_v, Wl1v, nullptr, g_v1, g_gate, 3*Nn, A_V1, b-2*NBs);
}

// phase B, layer 0: l2_s (silu/gate) | l2_v (raw o_v, sc_v==0)
__global__ __launch_bounds__(256, 2)
void k_phB0(const float* __restrict__ Wl2s, const float* __restrict__ Wl2v){
    __shared__ float sm[16*129 + 16*96];
    int b = blockIdx.x;
    if (b < NBs) gemm_body<96,96,2>(sm, g_as, Wl2s, g_scs, nullptr, nullptr, Nn, A_O, b);
    else         gemm_body<96,32,0>(sm, g_av, Wl2v, nullptr, g_v, nullptr, 3*Nn, A_O, b-NBs);
}

// phase B, layer 1: l2_s only
__global__ __launch_bounds__(256, 2)
void k_phB1(const float* __restrict__ Wl2s){
    __shared__ float sm[16*129 + 16*96];
    gemm_body<96,96,2>(sm, g_as, Wl2s, g_scs, nullptr, nullptr, Nn, A_O, blockIdx.x);
}

// ---------------- gather ----------------
// LAYER 0: v==0 -> no ve loads; as2=0; av col-2 block = 0
// LAYER 1: av not needed (v unused downstream) -> as only
template<int LAYER>
__global__ void k_gather(const float* __restrict__ dR, const int* __restrict__ senders){
    int n = blockIdx.x*8 + threadIdx.y;
    if (n >= Nn) return;
    int l = threadIdx.x;
    const __half2* tb_base = g_tabh + LAYER*(TAB*192);
    int beg = g_off[n], end = g_off[n+1];
    float as0 = 0.f, as1 = 0.f, as2 = 0.f;
    float av00=0,av01=0, av10=0,av11=0, av20=0,av21=0;
    for (int p = beg; p < end; p++){
        int e = g_elist[p];
        float dx = dR[3*e+0], dy = dR[3*e+1], dz = dR[3*e+2];
        float r = sqrtf(dx*dx + dy*dy + dz*dz);
        if (r >= RMAXf) continue;
        float inv = 1.0f / fmaxf(r, 1e-6f);
        float shx = SQRT3f*dx*inv, shy = SQRT3f*dy*inv, shz = SQRT3f*dz*inv;
        int src = senders[e];
        float x = r * ((float)TAB / RMAXf);
        int gi = (int)x; if (gi > TAB-1) gi = TAB-1;
        float f = x - (float)gi;
        const __half2* t0 = tb_base + gi*192;
        __half2 h1a = t0[l], h1b = t0[32+l];
        float w1a = __low2float(h1a) + f*__high2float(h1a);
        float w1b = __low2float(h1b) + f*__high2float(h1b);
        float sea = g_s1[src*64 + l];
        float seb = g_s1[src*64 + 32 + l];
        as0 = fmaf(w1a, sea, as0);
        as1 = fmaf(w1b, seb, as1);
        if (LAYER == 0){
            __half2 h2a = t0[64+l], h2b = t0[96+l];
            float w2a = __low2float(h2a) + f*__high2float(h2a);
            float w2b = __low2float(h2b) + f*__high2float(h2b);
            float p2a = w2a*sea, p2b = w2b*seb;
            av00 = fmaf(p2a, shx, av00); av10 = fmaf(p2a, shy, av10); av20 = fmaf(p2a, shz, av20);
            av01 = fmaf(p2b, shx, av01); av11 = fmaf(p2b, shy, av11); av21 = fmaf(p2b, shz, av21);
        } else {
            __half2 h4 = t0[160+l];
            float w4 = __low2float(h4) + f*__high2float(h4);
            float ve0 = g_v1[src*96 +      l];
            float ve1 = g_v1[src*96 + 32 + l];
            float ve2 = g_v1[src*96 + 64 + l];
            float dv = ve0*shx + ve1*shy + ve2*shz;
            as2 = fmaf(w4*INV_SQRT3f, dv, as2);
        }
    }
    const float sc = 0.25f;
    g_as[n*96 +      l] = as0*sc;
    g_as[n*96 + 32 + l] = as1*sc;
    g_as[n*96 + 64 + l] = as2*sc;        // 0 at layer 0
    if (LAYER == 0){
        int b0 = n*288;
        g_av[b0 +       l] = av00*sc; g_av[b0 +  32+l] = av01*sc; g_av[b0 +  64+l] = 0.f;
        g_av[b0 +  96 + l] = av10*sc; g_av[b0 + 128+l] = av11*sc; g_av[b0 + 160+l] = 0.f;
        g_av[b0 + 192 + l] = av20*sc; g_av[b0 + 224+l] = av21*sc; g_av[b0 + 256+l] = 0.f;
    }
}

// ---------------- heads ----------------
__global__ void k_head(const float* __restrict__ nodes,
                       const float* __restrict__ Wen1, const float* __restrict__ Wen2,
                       const float* __restrict__ Wmag1, const float* __restrict__ Wmag2,
                       const float* __restrict__ sc_occ, const float* __restrict__ sh_occ,
                       const float* __restrict__ esc, const float* __restrict__ esh,
                       float* __restrict__ out){
    int n = blockIdx.x*8 + threadIdx.y;
    if (n >= Nn) return;
    int t = threadIdx.x;
    const float* s = g_s + n*64;
    float he = 0.f, hm = 0.f;
    #pragma unroll 8
    for (int i = 0; i < 64; i++){
        float si = s[i];
        he = fmaf(si, Wen1[i*32+t], he);
        hm = fmaf(si, Wmag1[i*32+t], hm);
    }
    he *= 0.125f; hm *= 0.125f;
    float pe  = he * Wen2[t];
    float pm0 = hm * Wmag2[t*2+0];
    float pm1 = hm * Wmag2[t*2+1];
    #pragma unroll
    for (int o = 16; o; o >>= 1){
        pe  += __shfl_down_sync(0xffffffffu, pe,  o);
        pm0 += __shfl_down_sync(0xffffffffu, pm0, o);
        pm1 += __shfl_down_sync(0xffffffffu, pm1, o);
    }
    if (t == 0){
        g_atomic[n] = esc[0] * (pe * 0.17677669529f) + esh[0];
        float a0 = nodes[n*4+0], a1 = nodes[n*4+1], a2 = nodes[n*4+2];
        float s0 = a0*sc_occ[0] + a1*sc_occ[2] + a2*sc_occ[4];
        float s1m= a0*sc_occ[1] + a1*sc_occ[3] + a2*sc_occ[5];
        float t0 = a0*sh_occ[0] + a1*sh_occ[2] + a2*sh_occ[4];
        float t1 = a0*sh_occ[1] + a1*sh_occ[3] + a2*sh_occ[5];
        out[Gg + n*2 + 0] = s0 *(pm0 * 0.17677669529f) + t0;
        out[Gg + n*2 + 1] = s1m*(pm1 * 0.17677669529f) + t1;
    }
}

__global__ void k_energy(const int* __restrict__ n_node, float* __restrict__ out){
    __shared__ float sm[256];
    int g = blockIdx.x, t = threadIdx.x;
    int start = 0;
    for (int q = 0; q < g; q++) start += n_node[q];
    int end = start + n_node[g];
    if (start > Nn) start = Nn;
    if (end > Nn) end = Nn;
    float acc = 0.f;
    for (int i = start + t; i < end; i += 256) acc += g_atomic[i];
    sm[t] = acc; __syncthreads();
    #pragma unroll
    for (int o = 128; o; o >>= 1){ if (t < o) sm[t] += sm[t+o]; __syncthreads(); }
    if (t == 0) out[g] = sm[0];
}

// ---------------- launch ----------------
extern "C" void kernel_launch(void* const* d_in, const int* in_sizes, int n_in,
                              void* d_out, int out_size){
    const float* nodes   = (const float*)d_in[0];
    const float* dR      = (const float*)d_in[1];
    const int*   senders = (const int*)  d_in[2];
    const int*   recv    = (const int*)  d_in[3];
    const int*   n_node  = (const int*)  d_in[4];
    const float* W_embed = (const float*)d_in[5];
    const float* W_sc_s  = (const float*)d_in[6];
    const float* W_l1_s  = (const float*)d_in[8];
    const float* W_l1_v  = (const float*)d_in[9];
    const float* Wr0     = (const float*)d_in[10];
    const float* Wr1     = (const float*)d_in[11];
    const float* Wr2     = (const float*)d_in[12];
    const float* W_l2_s  = (const float*)d_in[13];
    const float* W_l2_v  = (const float*)d_in[14];
    const float* W_en1   = (const float*)d_in[15];
    const float* W_en2   = (const float*)d_in[16];
    const float* W_mag1  = (const float*)d_in[17];
    const float* W_mag2  = (const float*)d_in[18];
    const float* sc_occ  = (const float*)d_in[19];
    const float* sh_occ  = (const float*)d_in[20];
    const float* esc     = (const float*)d_in[21];
    const float* esh     = (const float*)d_in[22];
    float* out = (float*)d_out;

    k_zero_init<<<(Nn + 255)/256, 256>>>();
    k_count<<<(Ee + 255)/256, 256>>>(recv);
    k_scan<<<1, 1024>>>();
    k_scatter<<<(Ee + 255)/256, 256>>>(recv);
    k_misc<<<SORT_NB + EMB_NB + TAB_NB, 256>>>(nodes, W_embed, Wr0, Wr1, Wr2);
    k_pack<<<(2*TAB*192 + 255)/256, 256>>>();

    // layer 0
    k_phA0<<<2*NBs, 256>>>(nodes, W_sc_s, W_l1_s);
    k_gather<0><<<(Nn + 7)/8, dim3(32, 8)>>>(dR, senders);
    k_phB0<<<NBs + NBv, 256>>>(W_l2_s, W_l2_v);
    // layer 1
    k_phA1<<<2*NBs + NBv, 256>>>(nodes, W_sc_s + 24576, W_l1_s + 4096, W_l1_v + 1024);
    k_gather<1><<<(Nn + 7)/8, dim3(32, 8)>>>(dR, senders);
    k_phB1<<<NBs, 256>>>(W_l2_s + 9216);

    k_head<<<(Nn + 7)/8, dim3(32, 8)>>>(nodes, W_en1, W_en2, W_mag1, W_mag2,
                                        sc_occ, sh_occ, esc, esh, out);
    k_energy<<<Gg, 256>>>(n_node, out);
}